// round 13
// baseline (speedup 1.0000x reference)
#include <cuda_runtime.h>
#include <cuda_bf16.h>
#include <stdint.h>

#define DEEP_IN 200
#define MAXB 16384
#define TILE_R 64

// ---------------- K2 dynamic smem layout (bytes) — identical to R12 --------
#define XHI    0
#define XLO    27648
#define WB0HI  55296
#define WB1HI  75776
#define WLODEL 10240
#define DSM    96256
#define H1HI   0
#define H1LO   17408
#define W2HI   55296
#define W2LO   72704

// pre-split weights (exact smem layouts)
__device__ __align__(16) __nv_bfloat16 g_w1chi[7 * 128 * 40];  // [7][128][40]
__device__ __align__(16) __nv_bfloat16 g_w1clo[7 * 128 * 40];
__device__ __align__(16) __nv_bfloat16 g_w2hi[64 * 136];
__device__ __align__(16) __nv_bfloat16 g_w2lo[64 * 136];

__device__ __forceinline__ uint32_t smem_u32(const void* p) {
    uint32_t a;
    asm("{ .reg .u64 t; cvta.to.shared.u64 t, %1; cvt.u32.u64 %0, t; }"
        : "=r"(a) : "l"(p));
    return a;
}
#define LDMX4(r, addr) \
    asm volatile("ldmatrix.sync.aligned.m8n8.x4.shared.b16 {%0,%1,%2,%3}, [%4];" \
        : "=r"((r)[0]), "=r"((r)[1]), "=r"((r)[2]), "=r"((r)[3]) : "r"(addr))
#define MMA_BF16(d, a, b0, b1) \
    asm volatile("mma.sync.aligned.m16n8k16.row.col.f32.bf16.bf16.f32 " \
        "{%0,%1,%2,%3}, {%4,%5,%6,%7}, {%8,%9}, {%0,%1,%2,%3};" \
        : "+f"((d)[0]), "+f"((d)[1]), "+f"((d)[2]), "+f"((d)[3]) \
        : "r"((a)[0]), "r"((a)[1]), "r"((a)[2]), "r"((a)[3]), "r"(b0), "r"(b1))
#define CPA16(dst, src) \
    asm volatile("cp.async.cg.shared.global [%0], [%1], 16;" \
                 :: "r"((uint32_t)(dst)), "l"(src) : "memory")
#define CP_COMMIT() asm volatile("cp.async.commit_group;" ::: "memory")
#define CP_WAIT(n)  asm volatile("cp.async.wait_group %0;" :: "n"(n) : "memory")

__device__ __forceinline__ uint32_t packbf(float v0, float v1) {
    __nv_bfloat162 p = __floats2bfloat162_rn(v0, v1);
    return *(uint32_t*)&p;
}
__device__ __forceinline__ void store_split2(char* hi, char* lo, uint32_t off,
                                             float v0, float v1) {
    __nv_bfloat16 h0 = __float2bfloat16(v0), h1 = __float2bfloat16(v1);
    float l0 = v0 - __bfloat162float(h0), l1 = v1 - __bfloat162float(h1);
    *(uint32_t*)(hi + off) = packbf(__bfloat162float(h0), __bfloat162float(h1));
    *(uint32_t*)(lo + off) = packbf(l0, l1);
}
__device__ __forceinline__ void store_split_s(char* hi, char* lo, uint32_t off,
                                              float x) {
    __nv_bfloat16 h = __float2bfloat16(x);
    *(__nv_bfloat16*)(hi + off) = h;
    *(__nv_bfloat16*)(lo + off) = __float2bfloat16(x - __bfloat162float(h));
}
__device__ __forceinline__ void store_split_g(__nv_bfloat16* ph, __nv_bfloat16* pl,
                                              float x) {
    __nv_bfloat16 h = __float2bfloat16(x);
    *ph = h;
    *pl = __float2bfloat16(x - __bfloat162float(h));
}

// ===========================================================================
// K1: tiny weight-prep — split W1/W2 into exact smem layouts (hi/lo bf16)
// ===========================================================================
__global__ void deepfm_prep_k1(const float* __restrict__ W1,
                               const float* __restrict__ W2)
{
    const int gid = blockIdx.x * blockDim.x + threadIdx.x;
    if (gid < 7 * 128 * 20) {                 // W1 -> [7][128][40]
        const int c = gid / (128 * 20);
        const int rem = gid % (128 * 20);
        const int j = rem / 20, p = rem % 20;
        const int e0 = p * 2;
        float v0 = 0.f, v1 = 0.f;
        if (e0 < 32) {
            const int kg = c * 32 + e0;
            if (kg < DEEP_IN) {
                const float2 v = *(const float2*)(W1 + j * DEEP_IN + kg);
                v0 = v.x;
                if (kg + 1 < DEEP_IN) v1 = v.y;
            }
        }
        const int o = (c * 128 + j) * 40 + e0;
        store_split_g(g_w1chi + o,     g_w1clo + o,     v0);
        store_split_g(g_w1chi + o + 1, g_w1clo + o + 1, v1);
    } else if (gid < 7 * 128 * 20 + 64 * 68) {  // W2 -> [64][136]
        const int idx = gid - 7 * 128 * 20;
        const int j = idx / 68, p = idx % 68;
        const int k = p * 2;
        float v0 = 0.f, v1 = 0.f;
        if (k < 128) {
            const float2 v = *(const float2*)(W2 + j * 128 + k);
            v0 = v.x; v1 = v.y;
        }
        const int o = j * 136 + k;
        store_split_g(g_w2hi + o,     g_w2lo + o,     v0);
        store_split_g(g_w2hi + o + 1, g_w2lo + o + 1, v1);
    }
}

// issue cp.async for W1 chunk c into buffer b (hi+lo, 1280 x 16B)
__device__ __forceinline__ void cpa_chunk(uint32_t smb, int c, int b, int t) {
    const char* gh = (const char*)g_w1chi + c * 10240;
    const char* gl = (const char*)g_w1clo + c * 10240;
    const uint32_t dst = smb + (b ? WB1HI : WB0HI);
    for (int i = t; i < 640; i += 256) {
        CPA16(dst + i * 16,          gh + i * 16);
        CPA16(dst + WLODEL + i * 16, gl + i * 16);
    }
}

// ===========================================================================
// K2: fused gather + HMMA MLP; 64 rows/CTA, 256 threads, 2 CTAs/SM.
// Gather overlaps W1 chunk cp.asyncs and the co-resident CTA's MMA.
// ===========================================================================
__global__ __launch_bounds__(256, 2) void deepfm_fused_k2(
    const int* __restrict__ uid, const int* __restrict__ iid,
    const int* __restrict__ gen, const int* __restrict__ age,
    const int* __restrict__ occ,
    const int* __restrict__ gids, const float* __restrict__ gmask,
    const float* __restrict__ dense,
    const float* __restrict__ fo_user, const float* __restrict__ fo_item,
    const float* __restrict__ fo_gender, const float* __restrict__ fo_age,
    const float* __restrict__ fo_occ, const float* __restrict__ fo_genre,
    const float* __restrict__ emb_user, const float* __restrict__ emb_item,
    const float* __restrict__ emb_gender, const float* __restrict__ emb_age,
    const float* __restrict__ emb_occ, const float* __restrict__ emb_genre,
    const float* __restrict__ dense_W, const float* __restrict__ dense_b,
    const float* __restrict__ b1, const float* __restrict__ b2,
    const float* __restrict__ Wout, const float* __restrict__ bout,
    float* __restrict__ out, int B)
{
    extern __shared__ char sm[];
    __shared__ float base_s[TILE_R];
    __shared__ float b1s[128], b2s[64], wouts[64];
    __shared__ float part[4][TILE_R];

    const int t    = threadIdx.x;
    const int lane = t & 31;
    const int wrp  = t >> 5;        // 0..7
    const int wm   = wrp >> 2;      // 0..1
    const int rowbase = blockIdx.x * TILE_R;
    const uint32_t smb = smem_u32(sm);

    // ---- issue W1 chunk0/1 prefetches first --------------------------------
    cpa_chunk(smb, 0, 0, t); CP_COMMIT();
    cpa_chunk(smb, 1, 1, t); CP_COMMIT();

    if (t < 128)      b1s[t] = b1[t];
    else if (t < 192) b2s[t - 128] = b2[t - 128];
    else              wouts[t - 192] = Wout[t - 192];

    // ---- gather: warp w -> rows w*8..w*8+7, X hi/lo straight into smem -----
#pragma unroll
    for (int i = 0; i < 8; i++) {
        const int rl = wrp * 8 + i;
        const int r  = rowbase + rl;
        if (r >= B) continue;

        const int u  = uid[r];
        const int it = iid[r];
        const int g  = gen[r];
        const int a  = age[r];
        const int o  = occ[r];

        const float xu = emb_user  [u  * 32 + lane];
        const float xi = emb_item  [it * 32 + lane];
        const float xg = emb_gender[g  * 32 + lane];
        const float xa = emb_age   [a  * 32 + lane];
        const float xo = emb_occ   [o  * 32 + lane];

        float gsum = 0.f, msum = 0.f, fsum = 0.f;
#pragma unroll
        for (int k = 0; k < 6; k++) {
            const int   gid = gids [r * 6 + k];
            const float m   = gmask[r * 6 + k];
            gsum += m * emb_genre[gid * 32 + lane];
            msum += m;
            fsum += m * fo_genre[gid];
        }
        const float denom = fmaxf(msum, 1.0f);
        const float xge = gsum / denom;

        char* xh = sm + XHI;
        char* xl = sm + XLO;
        const uint32_t rb = rl * 432;
        store_split_s(xh, xl, rb + (lane) * 2,       xu);
        store_split_s(xh, xl, rb + (32 + lane) * 2,  xi);
        store_split_s(xh, xl, rb + (64 + lane) * 2,  xg);
        store_split_s(xh, xl, rb + (96 + lane) * 2,  xa);
        store_split_s(xh, xl, rb + (128 + lane) * 2, xo);
        store_split_s(xh, xl, rb + (160 + lane) * 2, xge);
        float dv = 0.f;
        if (lane < 8) {
            dv = dense[r * 8 + lane];
            store_split_s(xh, xl, rb + (192 + lane) * 2, dv);
        }
        if (lane < 16) {   // zero pads k = 200..215
            *(__nv_bfloat16*)(xh + rb + (200 + lane) * 2) = __float2bfloat16(0.f);
            *(__nv_bfloat16*)(xl + rb + (200 + lane) * 2) = __float2bfloat16(0.f);
        }

        const float s  = xu + xi + xg + xa + xo + xge;
        const float sq = xu*xu + xi*xi + xg*xg + xa*xa + xo*xo + xge*xge;
        float red = 0.5f * (s * s - sq);
        if (lane < 8) red += dv * dense_W[lane];
#pragma unroll
        for (int off = 16; off; off >>= 1)
            red += __shfl_xor_sync(0xffffffffu, red, off);
        if (lane == 0)
            base_s[rl] = fo_user[u] + fo_item[it] + fo_gender[g] + fo_age[a]
                       + fo_occ[o] + fsum / denom + dense_b[0] + red;
    }

    CP_WAIT(1);          // chunk0 landed (chunk1 still in flight)
    __syncthreads();

    // ---- Layer 1: 64x128x208 over 7 chunks (6x32 + 16 elems) ---------------
    const int wn = wrp & 3;
    float d[2][4][4];
#pragma unroll
    for (int r = 0; r < 2; r++)
#pragma unroll
        for (int nb = 0; nb < 4; nb++)
#pragma unroll
            for (int c = 0; c < 4; c++) d[r][nb][c] = 0.f;

    uint32_t aAddr[2];
#pragma unroll
    for (int r = 0; r < 2; r++)
        aAddr[r] = smb + (uint32_t)((wm * 32 + r * 16 + (lane & 15)) * 432
                 + (lane >> 4) * 16);
    const uint32_t bRow = (uint32_t)((wn * 32 + ((lane >> 4) << 3) + (lane & 7)) * 80
                 + ((lane >> 3) & 1) * 16);
    const uint32_t bRow16 = bRow + 16 * 80;

    for (int c = 0; c < 7; c++) {
        const uint32_t wb = smb + ((c & 1) ? WB1HI : WB0HI);
        const int nks = (c < 6) ? 2 : 1;
        for (int ks = 0; ks < nks; ks++) {
            const uint32_t kbA = c * 64 + ks * 32;
            const uint32_t kbB = ks * 32;
            uint32_t ah[2][4], al[2][4], bh[2][4], bl[2][4];
#pragma unroll
            for (int r = 0; r < 2; r++) {
                LDMX4(ah[r], aAddr[r] + XHI + kbA);
                LDMX4(al[r], aAddr[r] + (XLO - XHI) + kbA);
            }
            LDMX4(bh[0], wb + bRow + kbB);
            LDMX4(bl[0], wb + WLODEL + bRow + kbB);
            LDMX4(bh[1], wb + bRow16 + kbB);
            LDMX4(bl[1], wb + WLODEL + bRow16 + kbB);
#pragma unroll
            for (int r = 0; r < 2; r++)
#pragma unroll
                for (int h = 0; h < 2; h++)
#pragma unroll
                    for (int hf = 0; hf < 2; hf++) {
                        const int nb = h * 2 + hf;
                        MMA_BF16(d[r][nb], ah[r], bh[h][hf*2], bh[h][hf*2+1]);
                        MMA_BF16(d[r][nb], ah[r], bl[h][hf*2], bl[h][hf*2+1]);
                        MMA_BF16(d[r][nb], al[r], bh[h][hf*2], bh[h][hf*2+1]);
                    }
        }
        __syncthreads();
        if (c + 2 <= 6) { cpa_chunk(smb, c + 2, c & 1, t); CP_COMMIT(); }
        if (c < 6) {
            CP_WAIT(1);
            __syncthreads();
        }
    }

    // ---- issue W2 prefetch (lands during h1 epilogue) ----------------------
    {
        const char* gh = (const char*)g_w2hi;
        const char* gl = (const char*)g_w2lo;
        for (int i = t; i < 1088; i += 256) {
            CPA16(smb + W2HI + i * 16, gh + i * 16);
            CPA16(smb + W2LO + i * 16, gl + i * 16);
        }
        CP_COMMIT();
    }

    // ---- h1 epilogue: relu(d + b1) -> hi/lo [m][k] stride 272 --------------
#pragma unroll
    for (int r = 0; r < 2; r++)
#pragma unroll
        for (int nb = 0; nb < 4; nb++) {
            const int n = wn * 32 + nb * 8 + 2 * (lane & 3);
            const int m0 = wm * 32 + r * 16 + (lane >> 2);
            const float v0 = fmaxf(d[r][nb][0] + b1s[n], 0.f);
            const float v1 = fmaxf(d[r][nb][1] + b1s[n + 1], 0.f);
            store_split2(sm + H1HI, sm + H1LO, m0 * 272 + n * 2, v0, v1);
            const float v2 = fmaxf(d[r][nb][2] + b1s[n], 0.f);
            const float v3 = fmaxf(d[r][nb][3] + b1s[n + 1], 0.f);
            store_split2(sm + H1HI, sm + H1LO, (m0 + 8) * 272 + n * 2, v2, v3);
        }
    CP_WAIT(0);
    __syncthreads();

    // ---- Layer 2: 64x64x128 ------------------------------------------------
    {
        const int wn2 = wrp & 3;
        float d2[2][2][4];
#pragma unroll
        for (int r = 0; r < 2; r++)
#pragma unroll
            for (int nb = 0; nb < 2; nb++)
#pragma unroll
                for (int c = 0; c < 4; c++) d2[r][nb][c] = 0.f;

        uint32_t a2[2];
#pragma unroll
        for (int r = 0; r < 2; r++)
            a2[r] = smb + (uint32_t)((wm * 32 + r * 16 + (lane & 15)) * 272
                  + (lane >> 4) * 16);
        const uint32_t b2a = smb + W2HI
                  + (uint32_t)((wn2 * 16 + ((lane >> 4) << 3) + (lane & 7)) * 272
                  + ((lane >> 3) & 1) * 16);

#pragma unroll
        for (int ks = 0; ks < 8; ks++) {
            const uint32_t kb = ks * 32;
            uint32_t ah[2][4], al[2][4], bh[4], bl[4];
#pragma unroll
            for (int r = 0; r < 2; r++) {
                LDMX4(ah[r], a2[r] + H1HI + kb);
                LDMX4(al[r], a2[r] + (H1LO - H1HI) + kb);
            }
            LDMX4(bh, b2a + kb);
            LDMX4(bl, b2a + (W2LO - W2HI) + kb);
#pragma unroll
            for (int r = 0; r < 2; r++)
#pragma unroll
                for (int hf = 0; hf < 2; hf++) {
                    MMA_BF16(d2[r][hf], ah[r], bh[hf*2], bh[hf*2+1]);
                    MMA_BF16(d2[r][hf], ah[r], bl[hf*2], bl[hf*2+1]);
                    MMA_BF16(d2[r][hf], al[r], bh[hf*2], bh[hf*2+1]);
                }
        }

        // epilogue 2
#pragma unroll
        for (int r = 0; r < 2; r++) {
            float s_lo = 0.f, s_hi = 0.f;
#pragma unroll
            for (int nb = 0; nb < 2; nb++) {
                const int n = wn2 * 16 + nb * 8 + 2 * (lane & 3);
                s_lo += fmaxf(d2[r][nb][0] + b2s[n], 0.f)     * wouts[n]
                      + fmaxf(d2[r][nb][1] + b2s[n + 1], 0.f) * wouts[n + 1];
                s_hi += fmaxf(d2[r][nb][2] + b2s[n], 0.f)     * wouts[n]
                      + fmaxf(d2[r][nb][3] + b2s[n + 1], 0.f) * wouts[n + 1];
            }
#pragma unroll
            for (int off = 1; off <= 2; off <<= 1) {
                s_lo += __shfl_xor_sync(0xffffffffu, s_lo, off);
                s_hi += __shfl_xor_sync(0xffffffffu, s_hi, off);
            }
            if ((lane & 3) == 0) {
                const int m0 = wm * 32 + r * 16 + (lane >> 2);
                part[wn2][m0]     = s_lo;
                part[wn2][m0 + 8] = s_hi;
            }
        }
    }
    __syncthreads();

    if (t < TILE_R) {
        const int r = rowbase + t;
        if (r < B)
            out[r] = base_s[t] + part[0][t] + part[1][t] + part[2][t] + part[3][t]
                   + bout[0];
    }
}

// ---------------------------------------------------------------------------
extern "C" void kernel_launch(void* const* d_in, const int* in_sizes, int n_in,
                              void* d_out, int out_size)
{
    const int*   uid      = (const int*)  d_in[0];
    const int*   iid      = (const int*)  d_in[1];
    const int*   gen      = (const int*)  d_in[2];
    const int*   age      = (const int*)  d_in[3];
    const int*   occ      = (const int*)  d_in[4];
    const int*   gids     = (const int*)  d_in[5];
    const float* gmask    = (const float*)d_in[6];
    const float* dense    = (const float*)d_in[7];
    const float* fo_user  = (const float*)d_in[8];
    const float* fo_item  = (const float*)d_in[9];
    const float* fo_gender= (const float*)d_in[10];
    const float* fo_age   = (const float*)d_in[11];
    const float* fo_occ   = (const float*)d_in[12];
    const float* fo_genre = (const float*)d_in[13];
    const float* emb_user = (const float*)d_in[14];
    const float* emb_item = (const float*)d_in[15];
    const float* emb_gender=(const float*)d_in[16];
    const float* emb_age  = (const float*)d_in[17];
    const float* emb_occ  = (const float*)d_in[18];
    const float* emb_genre= (const float*)d_in[19];
    const float* dense_W  = (const float*)d_in[20];
    const float* dense_b  = (const float*)d_in[21];
    const float* W1       = (const float*)d_in[22];
    const float* b1       = (const float*)d_in[23];
    const float* W2       = (const float*)d_in[24];
    const float* b2       = (const float*)d_in[25];
    const float* Wout     = (const float*)d_in[26];
    const float* bout     = (const float*)d_in[27];
    float*       out      = (float*)d_out;

    const int B = in_sizes[0];

    // K1: weight prep (tiny)
    deepfm_prep_k1<<<87, 256>>>(W1, W2);

    // K2: fused gather + HMMA MLP
    {
        cudaFuncSetAttribute(deepfm_fused_k2,
                             cudaFuncAttributeMaxDynamicSharedMemorySize, DSM);
        const int blocks = (B + TILE_R - 1) / TILE_R;
        deepfm_fused_k2<<<blocks, 256, DSM>>>(
            uid, iid, gen, age, occ, gids, gmask, dense,
            fo_user, fo_item, fo_gender, fo_age, fo_occ, fo_genre,
            emb_user, emb_item, emb_gender, emb_age, emb_occ, emb_genre,
            dense_W, dense_b, b1, b2, Wout, bout, out, B);
    }
}

// round 15
// speedup vs baseline: 1.0984x; 1.0984x over previous
#include <cuda_runtime.h>
#include <cuda_bf16.h>
#include <stdint.h>

#define DEEP_IN 200
#define MAXB 16384
#define TILE_R 64
#define XROW 216              // padded X row (elems); 432 B

// ---------------- K2 dynamic smem layout (bytes) ---------------------------
#define XHI    0
#define XLO    27648
#define WB0HI  55296
#define WB1HI  75776
#define WLODEL 10240          // lo half offset within a WB buffer
#define DSM    96256
#define H1HI   0
#define H1LO   17408
#define W2HI   55296
#define W2LO   72704

// pre-split buffers (exact smem layouts)
__device__ __align__(16) __nv_bfloat16 g_xhi[(size_t)MAXB * XROW];
__device__ __align__(16) __nv_bfloat16 g_xlo[(size_t)MAXB * XROW];
__device__ __align__(16) __nv_bfloat16 g_w1chi[7 * 128 * 40];  // [7][128][40]
__device__ __align__(16) __nv_bfloat16 g_w1clo[7 * 128 * 40];
__device__ __align__(16) __nv_bfloat16 g_w2hi[64 * 136];
__device__ __align__(16) __nv_bfloat16 g_w2lo[64 * 136];
__device__ float g_base[MAXB];

__device__ __forceinline__ uint32_t smem_u32(const void* p) {
    uint32_t a;
    asm("{ .reg .u64 t; cvta.to.shared.u64 t, %1; cvt.u32.u64 %0, t; }"
        : "=r"(a) : "l"(p));
    return a;
}
#define LDMX4(r, addr) \
    asm volatile("ldmatrix.sync.aligned.m8n8.x4.shared.b16 {%0,%1,%2,%3}, [%4];" \
        : "=r"((r)[0]), "=r"((r)[1]), "=r"((r)[2]), "=r"((r)[3]) : "r"(addr))
#define MMA_BF16(d, a, b0, b1) \
    asm volatile("mma.sync.aligned.m16n8k16.row.col.f32.bf16.bf16.f32 " \
        "{%0,%1,%2,%3}, {%4,%5,%6,%7}, {%8,%9}, {%0,%1,%2,%3};" \
        : "+f"((d)[0]), "+f"((d)[1]), "+f"((d)[2]), "+f"((d)[3]) \
        : "r"((a)[0]), "r"((a)[1]), "r"((a)[2]), "r"((a)[3]), "r"(b0), "r"(b1))
#define CPA16(dst, src) \
    asm volatile("cp.async.cg.shared.global [%0], [%1], 16;" \
                 :: "r"((uint32_t)(dst)), "l"(src) : "memory")
#define CP_COMMIT() asm volatile("cp.async.commit_group;" ::: "memory")
#define CP_WAIT(n)  asm volatile("cp.async.wait_group %0;" :: "n"(n) : "memory")

__device__ __forceinline__ uint32_t packbf(float v0, float v1) {
    __nv_bfloat162 p = __floats2bfloat162_rn(v0, v1);
    return *(uint32_t*)&p;
}
__device__ __forceinline__ void store_split2(char* hi, char* lo, uint32_t off,
                                             float v0, float v1) {
    __nv_bfloat16 h0 = __float2bfloat16(v0), h1 = __float2bfloat16(v1);
    float l0 = v0 - __bfloat162float(h0), l1 = v1 - __bfloat162float(h1);
    *(uint32_t*)(hi + off) = packbf(__bfloat162float(h0), __bfloat162float(h1));
    *(uint32_t*)(lo + off) = packbf(l0, l1);
}
__device__ __forceinline__ void store_split_g(__nv_bfloat16* ph, __nv_bfloat16* pl,
                                              float x) {
    __nv_bfloat16 h = __float2bfloat16(x);
    *ph = h;
    *pl = __float2bfloat16(x - __bfloat162float(h));
}

// ===========================================================================
// K1: gather + FM terms (one warp per row) + weight pre-split blocks
// ===========================================================================
__global__ void deepfm_gather_k1(
    const int* __restrict__ uid, const int* __restrict__ iid,
    const int* __restrict__ gen, const int* __restrict__ age,
    const int* __restrict__ occ,
    const int* __restrict__ gids, const float* __restrict__ gmask,
    const float* __restrict__ dense,
    const float* __restrict__ fo_user, const float* __restrict__ fo_item,
    const float* __restrict__ fo_gender, const float* __restrict__ fo_age,
    const float* __restrict__ fo_occ, const float* __restrict__ fo_genre,
    const float* __restrict__ emb_user, const float* __restrict__ emb_item,
    const float* __restrict__ emb_gender, const float* __restrict__ emb_age,
    const float* __restrict__ emb_occ, const float* __restrict__ emb_genre,
    const float* __restrict__ dense_W, const float* __restrict__ dense_b,
    const float* __restrict__ W1, const float* __restrict__ W2,
    int B, int nb1)
{
    if ((int)blockIdx.x >= nb1) {
        const int gid = (blockIdx.x - nb1) * blockDim.x + threadIdx.x;
        if (gid < 7 * 128 * 20) {                 // W1 -> [7][128][40]
            const int c = gid / (128 * 20);
            const int rem = gid % (128 * 20);
            const int j = rem / 20, p = rem % 20;
            const int e0 = p * 2;
            float v0 = 0.f, v1 = 0.f;
            if (e0 < 32) {
                const int kg = c * 32 + e0;
                if (kg < DEEP_IN) {
                    const float2 v = *(const float2*)(W1 + j * DEEP_IN + kg);
                    v0 = v.x;
                    if (kg + 1 < DEEP_IN) v1 = v.y;
                }
            }
            const int o = (c * 128 + j) * 40 + e0;
            store_split_g(g_w1chi + o,     g_w1clo + o,     v0);
            store_split_g(g_w1chi + o + 1, g_w1clo + o + 1, v1);
        } else if (gid < 7 * 128 * 20 + 64 * 68) {  // W2 -> [64][136]
            const int idx = gid - 7 * 128 * 20;
            const int j = idx / 68, p = idx % 68;
            const int k = p * 2;
            float v0 = 0.f, v1 = 0.f;
            if (k < 128) {
                const float2 v = *(const float2*)(W2 + j * 128 + k);
                v0 = v.x; v1 = v.y;
            }
            const int o = j * 136 + k;
            store_split_g(g_w2hi + o,     g_w2lo + o,     v0);
            store_split_g(g_w2hi + o + 1, g_w2lo + o + 1, v1);
        }
        return;
    }

    const int r    = (blockIdx.x * blockDim.x + threadIdx.x) >> 5;
    const int lane = threadIdx.x & 31;
    if (r >= B) return;

    const int u  = uid[r];
    const int it = iid[r];
    const int g  = gen[r];
    const int a  = age[r];
    const int o  = occ[r];

    const float xu = emb_user  [u  * 32 + lane];
    const float xi = emb_item  [it * 32 + lane];
    const float xg = emb_gender[g  * 32 + lane];
    const float xa = emb_age   [a  * 32 + lane];
    const float xo = emb_occ   [o  * 32 + lane];

    float gsum = 0.f, msum = 0.f, fsum = 0.f;
#pragma unroll
    for (int k = 0; k < 6; k++) {
        const int   gid = gids [r * 6 + k];
        const float m   = gmask[r * 6 + k];
        gsum += m * emb_genre[gid * 32 + lane];
        msum += m;
        fsum += m * fo_genre[gid];
    }
    const float denom = fmaxf(msum, 1.0f);
    const float xge = gsum / denom;

    __nv_bfloat16* xh = g_xhi + (size_t)r * XROW;
    __nv_bfloat16* xl = g_xlo + (size_t)r * XROW;
    store_split_g(xh + lane,        xl + lane,        xu);
    store_split_g(xh + 32 + lane,   xl + 32 + lane,   xi);
    store_split_g(xh + 64 + lane,   xl + 64 + lane,   xg);
    store_split_g(xh + 96 + lane,   xl + 96 + lane,   xa);
    store_split_g(xh + 128 + lane,  xl + 128 + lane,  xo);
    store_split_g(xh + 160 + lane,  xl + 160 + lane,  xge);
    float dv = 0.f;
    if (lane < 8) {
        dv = dense[r * 8 + lane];
        store_split_g(xh + 192 + lane, xl + 192 + lane, dv);
    }
    if (lane < 16) {   // zero pads k = 200..215
        xh[200 + lane] = __float2bfloat16(0.f);
        xl[200 + lane] = __float2bfloat16(0.f);
    }

    const float s  = xu + xi + xg + xa + xo + xge;
    const float sq = xu*xu + xi*xi + xg*xg + xa*xa + xo*xo + xge*xge;
    float red = 0.5f * (s * s - sq);
    if (lane < 8) red += dv * dense_W[lane];
#pragma unroll
    for (int off = 16; off; off >>= 1)
        red += __shfl_xor_sync(0xffffffffu, red, off);
    if (lane == 0)
        g_base[r] = fo_user[u] + fo_item[it] + fo_gender[g] + fo_age[a]
                  + fo_occ[o] + fsum / denom + dense_b[0] + red;
}

// issue cp.async for W1 chunk c into buffer b (hi+lo, 1280 x 16B)
__device__ __forceinline__ void cpa_chunk(uint32_t smb, int c, int b, int t) {
    const char* gh = (const char*)g_w1chi + c * 10240;
    const char* gl = (const char*)g_w1clo + c * 10240;
    const uint32_t dst = smb + (b ? WB1HI : WB0HI);
    for (int i = t; i < 640; i += 256) {
        CPA16(dst + i * 16,          gh + i * 16);
        CPA16(dst + WLODEL + i * 16, gl + i * 16);
    }
}

// ===========================================================================
// K2: HMMA MLP, 64 rows/CTA, 256 threads, 2 CTAs/SM, cp.async double-buffered
//     ONE barrier per mainloop chunk (wait-then-sync merge).
// ===========================================================================
__global__ __launch_bounds__(256, 2) void deepfm_mlp_k2(
    const float* __restrict__ b1, const float* __restrict__ b2,
    const float* __restrict__ Wout, const float* __restrict__ bout,
    float* __restrict__ out, int B)
{
    extern __shared__ char sm[];
    __shared__ float base_s[TILE_R];
    __shared__ float b1s[128], b2s[64], wouts[64];
    __shared__ float part[4][TILE_R];

    const int t    = threadIdx.x;
    const int lane = t & 31;
    const int wrp  = t >> 5;        // 0..7
    const int wm   = wrp >> 2;      // 0..1
    const int rowbase = blockIdx.x * TILE_R;
    const uint32_t smb = smem_u32(sm);

    // ---- prologue: issue all prefetches ------------------------------------
    {
        const char* gh = (const char*)g_xhi + (size_t)rowbase * 432;
        const char* gl = (const char*)g_xlo + (size_t)rowbase * 432;
        for (int i = t; i < 1728; i += 256) {
            CPA16(smb + XHI + i * 16, gh + i * 16);
            CPA16(smb + XLO + i * 16, gl + i * 16);
        }
        CP_COMMIT();
    }
    cpa_chunk(smb, 0, 0, t); CP_COMMIT();
    cpa_chunk(smb, 1, 1, t); CP_COMMIT();

    if (t < 128)      b1s[t] = b1[t];
    else if (t < 192) b2s[t - 128] = b2[t - 128];
    else              wouts[t - 192] = Wout[t - 192];
    if (t < TILE_R && rowbase + t < B) base_s[t] = g_base[rowbase + t];

    CP_WAIT(1);          // X + chunk0 landed (chunk1 may be in flight)
    __syncthreads();

    // ---- Layer 1: 64x128x208 over 7 chunks (6x32 + 16 elems) ---------------
    const int wn = wrp & 3;
    float d[2][4][4];
#pragma unroll
    for (int r = 0; r < 2; r++)
#pragma unroll
        for (int nb = 0; nb < 4; nb++)
#pragma unroll
            for (int c = 0; c < 4; c++) d[r][nb][c] = 0.f;

    uint32_t aAddr[2];
#pragma unroll
    for (int r = 0; r < 2; r++)
        aAddr[r] = smb + (uint32_t)((wm * 32 + r * 16 + (lane & 15)) * 432
                 + (lane >> 4) * 16);
    const uint32_t bRow = (uint32_t)((wn * 32 + ((lane >> 4) << 3) + (lane & 7)) * 80
                 + ((lane >> 3) & 1) * 16);
    const uint32_t bRow16 = bRow + 16 * 80;

    for (int c = 0; c < 7; c++) {
        const uint32_t wb = smb + ((c & 1) ? WB1HI : WB0HI);
        const int nks = (c < 6) ? 2 : 1;
        for (int ks = 0; ks < nks; ks++) {
            const uint32_t kbA = c * 64 + ks * 32;
            const uint32_t kbB = ks * 32;
            uint32_t ah[2][4], al[2][4], bh[2][4], bl[2][4];
#pragma unroll
            for (int r = 0; r < 2; r++) {
                LDMX4(ah[r], aAddr[r] + XHI + kbA);
                LDMX4(al[r], aAddr[r] + (XLO - XHI) + kbA);
            }
            LDMX4(bh[0], wb + bRow + kbB);
            LDMX4(bl[0], wb + WLODEL + bRow + kbB);
            LDMX4(bh[1], wb + bRow16 + kbB);
            LDMX4(bl[1], wb + WLODEL + bRow16 + kbB);
#pragma unroll
            for (int r = 0; r < 2; r++)
#pragma unroll
                for (int h = 0; h < 2; h++)
#pragma unroll
                    for (int hf = 0; hf < 2; hf++) {
                        const int nb = h * 2 + hf;
                        MMA_BF16(d[r][nb], ah[r], bh[h][hf*2], bh[h][hf*2+1]);
                        MMA_BF16(d[r][nb], ah[r], bl[h][hf*2], bl[h][hf*2+1]);
                        MMA_BF16(d[r][nb], al[r], bh[h][hf*2], bh[h][hf*2+1]);
                    }
        }
        // merged wait+sync: own c+1 copies done, then barrier => everyone's
        // copies visible AND all reads of buffer (c&1) complete -> safe reuse
        if (c < 6) CP_WAIT(0);
        __syncthreads();
        if (c + 2 <= 6) { cpa_chunk(smb, c + 2, c & 1, t); CP_COMMIT(); }
    }

    // ---- issue W2 prefetch (lands during h1 epilogue) ----------------------
    {
        const char* gh = (const char*)g_w2hi;
        const char* gl = (const char*)g_w2lo;
        for (int i = t; i < 1088; i += 256) {
            CPA16(smb + W2HI + i * 16, gh + i * 16);
            CPA16(smb + W2LO + i * 16, gl + i * 16);
        }
        CP_COMMIT();
    }

    // ---- h1 epilogue: relu(d + b1) -> hi/lo [m][k] stride 272 --------------
#pragma unroll
    for (int r = 0; r < 2; r++)
#pragma unroll
        for (int nb = 0; nb < 4; nb++) {
            const int n = wn * 32 + nb * 8 + 2 * (lane & 3);
            const int m0 = wm * 32 + r * 16 + (lane >> 2);
            const float v0 = fmaxf(d[r][nb][0] + b1s[n], 0.f);
            const float v1 = fmaxf(d[r][nb][1] + b1s[n + 1], 0.f);
            store_split2(sm + H1HI, sm + H1LO, m0 * 272 + n * 2, v0, v1);
            const float v2 = fmaxf(d[r][nb][2] + b1s[n], 0.f);
            const float v3 = fmaxf(d[r][nb][3] + b1s[n + 1], 0.f);
            store_split2(sm + H1HI, sm + H1LO, (m0 + 8) * 272 + n * 2, v2, v3);
        }
    CP_WAIT(0);
    __syncthreads();

    // ---- Layer 2: 64x64x128 ------------------------------------------------
    {
        const int wn2 = wrp & 3;
        float d2[2][2][4];
#pragma unroll
        for (int r = 0; r < 2; r++)
#pragma unroll
            for (int nb = 0; nb < 2; nb++)
#pragma unroll
                for (int c = 0; c < 4; c++) d2[r][nb][c] = 0.f;

        uint32_t a2[2];
#pragma unroll
        for (int r = 0; r < 2; r++)
            a2[r] = smb + (uint32_t)((wm * 32 + r * 16 + (lane & 15)) * 272
                  + (lane >> 4) * 16);
        const uint32_t b2a = smb + W2HI
                  + (uint32_t)((wn2 * 16 + ((lane >> 4) << 3) + (lane & 7)) * 272
                  + ((lane >> 3) & 1) * 16);

#pragma unroll
        for (int ks = 0; ks < 8; ks++) {
            const uint32_t kb = ks * 32;
            uint32_t ah[2][4], al[2][4], bh[4], bl[4];
#pragma unroll
            for (int r = 0; r < 2; r++) {
                LDMX4(ah[r], a2[r] + H1HI + kb);
                LDMX4(al[r], a2[r] + (H1LO - H1HI) + kb);
            }
            LDMX4(bh, b2a + kb);
            LDMX4(bl, b2a + (W2LO - W2HI) + kb);
#pragma unroll
            for (int r = 0; r < 2; r++)
#pragma unroll
                for (int hf = 0; hf < 2; hf++) {
                    MMA_BF16(d2[r][hf], ah[r], bh[hf*2], bh[hf*2+1]);
                    MMA_BF16(d2[r][hf], ah[r], bl[hf*2], bl[hf*2+1]);
                    MMA_BF16(d2[r][hf], al[r], bh[hf*2], bh[hf*2+1]);
                }
        }

        // epilogue 2
#pragma unroll
        for (int r = 0; r < 2; r++) {
            float s_lo = 0.f, s_hi = 0.f;
#pragma unroll
            for (int nb = 0; nb < 2; nb++) {
                const int n = wn2 * 16 + nb * 8 + 2 * (lane & 3);
                s_lo += fmaxf(d2[r][nb][0] + b2s[n], 0.f)     * wouts[n]
                      + fmaxf(d2[r][nb][1] + b2s[n + 1], 0.f) * wouts[n + 1];
                s_hi += fmaxf(d2[r][nb][2] + b2s[n], 0.f)     * wouts[n]
                      + fmaxf(d2[r][nb][3] + b2s[n + 1], 0.f) * wouts[n + 1];
            }
#pragma unroll
            for (int off = 1; off <= 2; off <<= 1) {
                s_lo += __shfl_xor_sync(0xffffffffu, s_lo, off);
                s_hi += __shfl_xor_sync(0xffffffffu, s_hi, off);
            }
            if ((lane & 3) == 0) {
                const int m0 = wm * 32 + r * 16 + (lane >> 2);
                part[wn2][m0]     = s_lo;
                part[wn2][m0 + 8] = s_hi;
            }
        }
    }
    __syncthreads();

    if (t < TILE_R) {
        const int r = rowbase + t;
        if (r < B)
            out[r] = base_s[t] + part[0][t] + part[1][t] + part[2][t] + part[3][t]
                   + bout[0];
    }
}

// ---------------------------------------------------------------------------
extern "C" void kernel_launch(void* const* d_in, const int* in_sizes, int n_in,
                              void* d_out, int out_size)
{
    const int*   uid      = (const int*)  d_in[0];
    const int*   iid      = (const int*)  d_in[1];
    const int*   gen      = (const int*)  d_in[2];
    const int*   age      = (const int*)  d_in[3];
    const int*   occ      = (const int*)  d_in[4];
    const int*   gids     = (const int*)  d_in[5];
    const float* gmask    = (const float*)d_in[6];
    const float* dense    = (const float*)d_in[7];
    const float* fo_user  = (const float*)d_in[8];
    const float* fo_item  = (const float*)d_in[9];
    const float* fo_gender= (const float*)d_in[10];
    const float* fo_age   = (const float*)d_in[11];
    const float* fo_occ   = (const float*)d_in[12];
    const float* fo_genre = (const float*)d_in[13];
    const float* emb_user = (const float*)d_in[14];
    const float* emb_item = (const float*)d_in[15];
    const float* emb_gender=(const float*)d_in[16];
    const float* emb_age  = (const float*)d_in[17];
    const float* emb_occ  = (const float*)d_in[18];
    const float* emb_genre= (const float*)d_in[19];
    const float* dense_W  = (const float*)d_in[20];
    const float* dense_b  = (const float*)d_in[21];
    const float* W1       = (const float*)d_in[22];
    const float* b1       = (const float*)d_in[23];
    const float* W2       = (const float*)d_in[24];
    const float* b2       = (const float*)d_in[25];
    const float* Wout     = (const float*)d_in[26];
    const float* bout     = (const float*)d_in[27];
    float*       out      = (float*)d_out;

    const int B = in_sizes[0];

    // K1: gather (one warp per row) + weight-prep blocks
    {
        const int threads = 256;
        const int rowsPerBlock = threads / 32;
        const int nb1 = (B + rowsPerBlock - 1) / rowsPerBlock;
        deepfm_gather_k1<<<nb1 + 90, threads>>>(
            uid, iid, gen, age, occ, gids, gmask, dense,
            fo_user, fo_item, fo_gender, fo_age, fo_occ, fo_genre,
            emb_user, emb_item, emb_gender, emb_age, emb_occ, emb_genre,
            dense_W, dense_b, W1, W2, B, nb1);
    }
    // K2: HMMA MLP (64 rows/CTA, 2 CTAs/SM, cp.async pipeline, 1 barrier/chunk)
    {
        cudaFuncSetAttribute(deepfm_mlp_k2,
                             cudaFuncAttributeMaxDynamicSharedMemorySize, DSM);
        const int blocks = (B + TILE_R - 1) / TILE_R;
        deepfm_mlp_k2<<<blocks, 256, DSM>>>(b1, b2, Wout, bout, out, B);
    }
}